// round 11
// baseline (speedup 1.0000x reference)
#include <cuda_runtime.h>
#include <math.h>
#include <stdint.h>

#define S_LEN 16384
#define I_DIM 64
#define R_DIM 2048
#define H_DIM 128
#define O_DIM 50
#define NBLK  128
#define ROWS_PER_BLK 16   // 128*16 = 2048
#define NTHR  512
#define GT    128         // timesteps per block in output phase
#define KT    64

// ---------------- device scratch (static; no allocations) ----------------
__device__ float g_states[(size_t)S_LEN * R_DIM];   // 134 MB; also the h exchange
__device__ float g_Wc[O_DIM * R_DIM];               // folded fc2@fc1
__device__ float g_bc[O_DIM];                       // folded bias
__device__ unsigned g_flag[NBLK * 32];              // per-block flag, 128B apart; monotone
__device__ unsigned g_fbas[NBLK];                   // per-launch snapshot of flags

// packed f32x2 FMA: d = a*b + d (sm_100+; only reachable via PTX)
__device__ __forceinline__ void ffma2(uint64_t& d, uint64_t a, uint64_t b) {
    asm("fma.rn.f32x2 %0, %1, %2, %0;" : "+l"(d) : "l"(a), "l"(b));
}
__device__ __forceinline__ unsigned ld_relaxed_u32(const unsigned* p) {
    unsigned v;
    asm volatile("ld.relaxed.gpu.global.u32 %0, [%1];" : "=r"(v) : "l"(p) : "memory");
    return v;
}
__device__ __forceinline__ void st_release_u32(unsigned* p, unsigned v) {
    asm volatile("st.release.gpu.global.u32 [%0], %1;" :: "l"(p), "r"(v) : "memory");
}
__device__ __forceinline__ void fence_acq() {
    asm volatile("fence.acq_rel.gpu;" ::: "memory");
}
// 16B L2 (cache-global) load as two packed u64
__device__ __forceinline__ void ldcg_v2u64(const void* p, uint64_t& a, uint64_t& b) {
    asm volatile("ld.global.cg.v2.u64 {%0,%1}, [%2];" : "=l"(a), "=l"(b) : "l"(p) : "memory");
}
__device__ __forceinline__ void stcg_f32(float* p, float v) {
    asm volatile("st.global.cg.f32 [%0], %1;" :: "l"(p), "f"(v) : "memory");
}

// snapshot all 128 flags BEFORE the persistent kernel (replay/wrap safe bases)
__global__ void prep_kernel() {
    if (threadIdx.x < NBLK) g_fbas[threadIdx.x] = g_flag[threadIdx.x * 32];
}

// ---------------- fused persistent kernel ----------------
union SmemU {
    float psum[2][ROWS_PER_BLK][4];                            // double-buffered
    struct { float s[GT][KT + 1]; float wc[O_DIM][KT]; } gemm; // 46 KB
};

__global__ void __launch_bounds__(NTHR, 1) fused_kernel(
    const float* __restrict__ x,      // [S,64]
    const float* __restrict__ Win,    // [2048,64]
    const float* __restrict__ W,      // [2048,2048]
    const float* __restrict__ fc1_w,  // [128,2048]
    const float* __restrict__ fc1_b,  // [128]
    const float* __restrict__ fc2_w,  // [50,128]
    const float* __restrict__ fc2_b,  // [50]
    float* __restrict__ out)          // [S,50]
{
    __shared__ SmemU sm;

    const int tid  = threadIdx.x;
    const int lane = tid & 31;
    const int wrp  = tid >> 5;          // 0..15
    const int grp  = tid >> 7;          // 0..3
    const int tg   = tid & 127;         // 0..127
    const int wig  = wrp & 3;           // warp-in-group
    const int rbase = blockIdx.x * ROWS_PER_BLK;

    // dataflow bookkeeping: this lane waits on producer block pb every step
    const int pb = 8 * wig + (lane & 7) + 32 * (lane >> 3);   // 32 distinct per warp
    const unsigned pb_base  = __ldg(&g_fbas[pb]);
    const unsigned* pb_flag = &g_flag[pb * 32];
    const unsigned own_base = __ldg(&g_fbas[blockIdx.x]);
    unsigned* const own_flag = &g_flag[blockIdx.x * 32];

    // ---- Phase 0: W slice -> registers; Win fold weights; Wc/bc fold
    uint64_t w2[4][8];
#pragma unroll
    for (int r = 0; r < 4; r++) {
        const ulonglong2* Wrow = (const ulonglong2*)(W + (size_t)(rbase + grp * 4 + r) * R_DIM);
#pragma unroll
        for (int j = 0; j < 4; j++) {
            ulonglong2 v = Wrow[tg + 128 * j];
            w2[r][2 * j]     = v.x;
            w2[r][2 * j + 1] = v.y;
        }
    }
    float wr[4] = {0.f, 0.f, 0.f, 0.f};
    if (tg < I_DIM) {
#pragma unroll
        for (int r = 0; r < 4; r++)
            wr[r] = __ldg(&Win[(size_t)(rbase + grp * 4 + r) * I_DIM + tg]);
    }
    // Wc fold: this block computes columns [rbase, rbase+16) for all 50 outputs
    for (int idx = tid; idx < O_DIM * ROWS_PER_BLK; idx += NTHR) {
        const int o  = idx >> 4;
        const int rr = idx & 15;
        float a = 0.f;
#pragma unroll 8
        for (int h = 0; h < H_DIM; h++)
            a += __ldg(&fc2_w[o * H_DIM + h]) * __ldg(&fc1_w[(size_t)h * R_DIM + rbase + rr]);
        g_Wc[o * R_DIM + rbase + rr] = a;
    }
    if (blockIdx.x == 0 && tid < O_DIM) {
        float b = __ldg(&fc2_b[tid]);
#pragma unroll 8
        for (int h = 0; h < H_DIM; h++) b += __ldg(&fc2_w[tid * H_DIM + h]) * __ldg(&fc1_b[h]);
        g_bc[tid] = b;
    }

    // ---- Phase 1: dataflow scan (per-warp waits on 32 producer flags; no global bar)
    float xv_next = (tg < I_DIM) ? __ldg(&x[tg]) : 0.f;   // x[0]
    float hold_reg = 0.0f;                                 // warp0 lanes<16

    for (int t = 0; t < S_LEN; t++) {
        const float xv = xv_next;
        if (t + 1 < S_LEN && tg < I_DIM) xv_next = __ldg(&x[(size_t)(t + 1) * I_DIM + tg]);

        uint64_t h2[8];
        if (t > 0) {
            // wait for my 32 producers to have published step t-1 (flag >= base+t)
            const unsigned tgt = pb_base + (unsigned)t;
            bool done = ((int)(ld_relaxed_u32(pb_flag) - tgt) >= 0);
            while (!__all_sync(0xffffffffu, done)) {
                if (!done) done = ((int)(ld_relaxed_u32(pb_flag) - tgt) >= 0);
            }
            fence_acq();
            const float4* hp = (const float4*)(g_states + (size_t)(t - 1) * R_DIM);
#pragma unroll
            for (int j = 0; j < 4; j++)
                ldcg_v2u64(hp + tg + 128 * j, h2[2 * j], h2[2 * j + 1]);
        } else {
#pragma unroll
            for (int j = 0; j < 8; j++) h2[j] = 0ull;
        }

        float acc[4];
#pragma unroll
        for (int r = 0; r < 4; r++) {
            float2 seed = make_float2(wr[r] * xv, 0.f);   // xin folded in
            uint64_t a2 = *(uint64_t*)&seed;
#pragma unroll
            for (int j = 0; j < 8; j++) ffma2(a2, w2[r][j], h2[j]);
            float2 f = *(float2*)&a2;
            acc[r] = f.x + f.y;
        }
#pragma unroll
        for (int r = 0; r < 4; r++) {
            float a = acc[r];
#pragma unroll
            for (int s = 16; s > 0; s >>= 1) a += __shfl_xor_sync(0xffffffffu, a, s);
            if (lane == 0) sm.psum[t & 1][grp * 4 + r][wig] = a;
        }
        __syncthreads();   // psum[t&1] complete; also orders phase-0 Wc stores at t=0

        // finalize + publish by warp 0 (no block-wide wait; others roll on)
        if (wrp == 0) {
            if (lane < ROWS_PER_BLK) {
                const float4 ps = *(const float4*)sm.psum[t & 1][lane];
                float v = (ps.x + ps.y) + (ps.z + ps.w);
                v = fminf(15.f, fmaxf(-15.f, v));
                const float e  = __expf(2.f * v);
                const float th = __fdividef(e - 1.f, e + 1.f);
                const float hn = 0.5f * hold_reg + 0.5f * th;
                hold_reg = hn;
                stcg_f32(&g_states[(size_t)t * R_DIM + rbase + lane], hn);  // publish data
            }
            __syncwarp(0xffffffffu);
            if (lane == 0) st_release_u32(own_flag, own_base + (unsigned)t + 1u);
        }
        // psum WAR: double buffer + the fact that warp0 re-arrives at the next
        // bar only after its finalize read -> writes to buf (t&1) at t+2 are safe
    }

    // ---- full fence: wait until ALL 128 blocks have published step S_LEN-1
    {
        __syncthreads();
        if (wrp == 0) {
            const unsigned tgt0 = __ldg(&g_fbas[lane])      + (unsigned)S_LEN;
            const unsigned tgt1 = __ldg(&g_fbas[lane + 32]) + (unsigned)S_LEN;
            const unsigned tgt2 = __ldg(&g_fbas[lane + 64]) + (unsigned)S_LEN;
            const unsigned tgt3 = __ldg(&g_fbas[lane + 96]) + (unsigned)S_LEN;
            bool done = false;
            while (!__all_sync(0xffffffffu, done)) {
                if (!done)
                    done = ((int)(ld_relaxed_u32(&g_flag[lane * 32])        - tgt0) >= 0)
                         & ((int)(ld_relaxed_u32(&g_flag[(lane + 32) * 32]) - tgt1) >= 0)
                         & ((int)(ld_relaxed_u32(&g_flag[(lane + 64) * 32]) - tgt2) >= 0)
                         & ((int)(ld_relaxed_u32(&g_flag[(lane + 96) * 32]) - tgt3) >= 0);
            }
            fence_acq();
        }
        __syncthreads();
    }

    // ---- Phase 2: out = states @ Wc^T + bc   (block handles GT timesteps)
    {
        const int t0 = blockIdx.x * GT;
        const int r  = tid & 127;            // row in tile
        const int oq = tid >> 7;             // 0..3
        const int OB = 13;                   // ceil(50/4)
        const int o0 = oq * OB;

        float acc[13];
#pragma unroll
        for (int i = 0; i < 13; i++) acc[i] = 0.0f;

        for (int k0 = 0; k0 < R_DIM; k0 += KT) {
#pragma unroll
            for (int i = 0; i < 4; i++) {
                int idx = tid + NTHR * i;
                int rr = idx >> 4, c4 = idx & 15;
                float4 v = __ldcg((const float4*)(g_states + (size_t)(t0 + rr) * R_DIM + k0) + c4);
                sm.gemm.s[rr][4 * c4 + 0] = v.x;
                sm.gemm.s[rr][4 * c4 + 1] = v.y;
                sm.gemm.s[rr][4 * c4 + 2] = v.z;
                sm.gemm.s[rr][4 * c4 + 3] = v.w;
            }
            for (int idx = tid; idx < O_DIM * (KT / 4); idx += NTHR) {
                int rr = idx >> 4, c4 = idx & 15;
                float4 v = __ldcg((const float4*)(g_Wc + (size_t)rr * R_DIM + k0) + c4);
                ((float4*)&sm.gemm.wc[rr][0])[c4] = v;
            }
            __syncthreads();
#pragma unroll 4
            for (int kk = 0; kk < KT; kk++) {
                float sv = sm.gemm.s[r][kk];
#pragma unroll
                for (int i = 0; i < 13; i++) {
                    int o = o0 + i;
                    if (o < O_DIM) acc[i] += sv * sm.gemm.wc[o][kk];
                }
            }
            __syncthreads();
        }
#pragma unroll
        for (int i = 0; i < 13; i++) {
            int o = o0 + i;
            if (o < O_DIM) out[(size_t)(t0 + r) * O_DIM + o] = acc[i] + __ldcg(&g_bc[o]);
        }
    }
}

// ---------------- launcher ----------------
extern "C" void kernel_launch(void* const* d_in, const int* in_sizes, int n_in,
                              void* d_out, int out_size) {
    (void)in_sizes; (void)n_in; (void)out_size;
    const float* x     = (const float*)d_in[0];
    const float* Win   = (const float*)d_in[1];
    const float* W     = (const float*)d_in[2];
    const float* fc1_w = (const float*)d_in[3];
    const float* fc1_b = (const float*)d_in[4];
    const float* fc2_w = (const float*)d_in[5];
    const float* fc2_b = (const float*)d_in[6];
    float* out = (float*)d_out;

    prep_kernel<<<1, 128>>>();
    fused_kernel<<<NBLK, NTHR>>>(x, Win, W, fc1_w, fc1_b, fc2_w, fc2_b, out);
}

// round 12
// speedup vs baseline: 1.4754x; 1.4754x over previous
#include <cuda_runtime.h>
#include <math.h>
#include <stdint.h>

#define S_LEN 16384
#define I_DIM 64
#define R_DIM 2048
#define H_DIM 128
#define O_DIM 50
#define NBLK  128
#define ROWS_PER_BLK 16   // 128*16 = 2048
#define NTHR  512
#define GT    128         // timesteps per block in output phase
#define KT    64

// ---------------- device scratch (static; no allocations) ----------------
__device__ float g_states[(size_t)S_LEN * R_DIM];   // 134 MB; also the h exchange
__device__ float g_Wc[O_DIM * R_DIM];               // folded fc2@fc1
__device__ float g_bc[O_DIM];                       // folded bias
__device__ unsigned g_count = 0;                    // monotone across replays
__device__ unsigned g_base  = 0;                    // snapshot for this launch

// packed f32x2 FMA: d = a*b + d (sm_100+; only reachable via PTX)
__device__ __forceinline__ void ffma2(uint64_t& d, uint64_t a, uint64_t b) {
    asm("fma.rn.f32x2 %0, %1, %2, %0;" : "+l"(d) : "l"(a), "l"(b));
}
__device__ __forceinline__ unsigned ld_relaxed_u32(const unsigned* p) {
    unsigned v;
    asm volatile("ld.relaxed.gpu.global.u32 %0, [%1];" : "=r"(v) : "l"(p) : "memory");
    return v;
}
__device__ __forceinline__ void fence_acq() {
    asm volatile("fence.acq_rel.gpu;" ::: "memory");
}
__device__ __forceinline__ void red_release_add(unsigned* p, unsigned v) {
    asm volatile("red.release.gpu.global.add.u32 [%0], %1;" :: "l"(p), "r"(v) : "memory");
}
// 16B L2 (cache-global) load as two packed u64
__device__ __forceinline__ void ldcg_v2u64(const void* p, uint64_t& a, uint64_t& b) {
    asm volatile("ld.global.cg.v2.u64 {%0,%1}, [%2];" : "=l"(a), "=l"(b) : "l"(p) : "memory");
}
__device__ __forceinline__ void stcg_f32(float* p, float v) {
    asm volatile("st.global.cg.f32 [%0], %1;" :: "l"(p), "f"(v) : "memory");
}
__device__ __forceinline__ float tanh_approx(float v) {
    float r;
    asm("tanh.approx.f32 %0, %1;" : "=f"(r) : "f"(v));
    return r;
}

// snapshot the barrier counter BEFORE the persistent kernel starts, so every
// block derives identical targets (kills start-skew races; replay/wrap safe).
__global__ void prep_kernel() { g_base = g_count; }

// ---------------- fused persistent kernel ----------------
union SmemU {
    float psum[ROWS_PER_BLK][4];                               // scan phase
    struct { float s[GT][KT + 1]; float wc[O_DIM][KT]; } gemm; // 46 KB
};

__global__ void __launch_bounds__(NTHR, 1) fused_kernel(
    const float* __restrict__ x,      // [S,64]
    const float* __restrict__ Win,    // [2048,64]
    const float* __restrict__ W,      // [2048,2048]
    const float* __restrict__ fc1_w,  // [128,2048]
    const float* __restrict__ fc1_b,  // [128]
    const float* __restrict__ fc2_w,  // [50,128]
    const float* __restrict__ fc2_b,  // [50]
    float* __restrict__ out)          // [S,50]
{
    __shared__ SmemU sm;

    const int tid  = threadIdx.x;
    const int lane = tid & 31;
    const int wrp  = tid >> 5;          // 0..15
    const int grp  = tid >> 7;          // 0..3
    const int tg   = tid & 127;         // 0..127
    const int wig  = wrp & 3;           // warp-in-group
    const int rbase = blockIdx.x * ROWS_PER_BLK;

    // identical for all blocks (set by prep_kernel); monotone + wrap-safe
    unsigned bar_tgt = g_base;

#define GBAR()                                                               \
    do {                                                                     \
        __syncthreads();                                                     \
        bar_tgt += NBLK;                                                     \
        if (wrp == 0) {                                                      \
            if (lane == 0) red_release_add(&g_count, 1u);                    \
            unsigned v;                                                      \
            do { v = ld_relaxed_u32(&g_count); } while ((int)(v - bar_tgt) < 0); \
            fence_acq();                                                     \
        }                                                                    \
        __syncthreads();                                                     \
    } while (0)

    // ---- Phase 0: W slice -> registers; Win fold weights; Wc/bc fold
    uint64_t w2[4][8];
#pragma unroll
    for (int r = 0; r < 4; r++) {
        const ulonglong2* Wrow = (const ulonglong2*)(W + (size_t)(rbase + grp * 4 + r) * R_DIM);
#pragma unroll
        for (int j = 0; j < 4; j++) {
            ulonglong2 v = Wrow[tg + 128 * j];
            w2[r][2 * j]     = v.x;
            w2[r][2 * j + 1] = v.y;
        }
    }
    float wr[4] = {0.f, 0.f, 0.f, 0.f};
    if (tg < I_DIM) {
#pragma unroll
        for (int r = 0; r < 4; r++)
            wr[r] = __ldg(&Win[(size_t)(rbase + grp * 4 + r) * I_DIM + tg]);
    }
    // Wc fold: this block computes columns [rbase, rbase+16) for all 50 outputs
    for (int idx = tid; idx < O_DIM * ROWS_PER_BLK; idx += NTHR) {
        const int o  = idx >> 4;
        const int rr = idx & 15;
        float a = 0.f;
#pragma unroll 8
        for (int h = 0; h < H_DIM; h++)
            a += __ldg(&fc2_w[o * H_DIM + h]) * __ldg(&fc1_w[(size_t)h * R_DIM + rbase + rr]);
        g_Wc[o * R_DIM + rbase + rr] = a;
    }
    if (blockIdx.x == 0 && tid < O_DIM) {
        float b = __ldg(&fc2_b[tid]);
#pragma unroll 8
        for (int h = 0; h < H_DIM; h++) b += __ldg(&fc2_w[tid * H_DIM + h]) * __ldg(&fc1_b[h]);
        g_bc[tid] = b;
    }

    GBAR();   // Wc/bc published (also aligns start skew)

    // ---- Phase 1: the scan (h exchanged through g_states rows; single store)
    float xv_next = (tg < I_DIM) ? __ldg(&x[tg]) : 0.f;   // x[0]
    float hold_reg = 0.0f;                                 // warp0 lanes<16

    for (int t = 0; t < S_LEN; t++) {
        const float xv = xv_next;
        if (t + 1 < S_LEN && tg < I_DIM) xv_next = __ldg(&x[(size_t)(t + 1) * I_DIM + tg]);

        uint64_t h2[8];
        if (t > 0) {
            const float4* hp = (const float4*)(g_states + (size_t)(t - 1) * R_DIM);
#pragma unroll
            for (int j = 0; j < 4; j++)
                ldcg_v2u64(hp + tg + 128 * j, h2[2 * j], h2[2 * j + 1]);
        } else {
#pragma unroll
            for (int j = 0; j < 8; j++) h2[j] = 0ull;
        }

        float acc[4];
#pragma unroll
        for (int r = 0; r < 4; r++) {
            float2 seed = make_float2(wr[r] * xv, 0.f);   // xin folded in
            uint64_t a2 = *(uint64_t*)&seed;
#pragma unroll
            for (int j = 0; j < 8; j++) ffma2(a2, w2[r][j], h2[j]);
            float2 f = *(float2*)&a2;
            acc[r] = f.x + f.y;
        }
#pragma unroll
        for (int r = 0; r < 4; r++) {
            float a = acc[r];
#pragma unroll
            for (int s = 16; s > 0; s >>= 1) a += __shfl_xor_sync(0xffffffffu, a, s);
            if (lane == 0) sm.psum[grp * 4 + r][wig] = a;
        }
        __syncthreads();

        // finalize + barrier fused into warp 0 (others park at bar.sync)
        bar_tgt += NBLK;
        if (wrp == 0) {
            if (lane < ROWS_PER_BLK) {
                const float4 ps = *(const float4*)sm.psum[lane];
                const float v  = (ps.x + ps.y) + (ps.z + ps.w);
                const float th = tanh_approx(v);                 // MUFU.TANH
                const float hn = 0.5f * hold_reg + 0.5f * th;
                hold_reg = hn;
                stcg_f32(&g_states[(size_t)t * R_DIM + rbase + lane], hn);  // single publish
            }
            __syncwarp(0xffffffffu);
            if (lane == 0) red_release_add(&g_count, 1u);   // release orders the store
            unsigned v;
            do { v = ld_relaxed_u32(&g_count); } while ((int)(v - bar_tgt) < 0);
            fence_acq();
        }
        __syncthreads();
    }

    GBAR();   // all states published (ordering for phase 2)

    // ---- Phase 2: out = states @ Wc^T + bc   (block handles GT timesteps)
    {
        const int t0 = blockIdx.x * GT;
        const int r  = tid & 127;            // row in tile
        const int oq = tid >> 7;             // 0..3
        const int OB = 13;                   // ceil(50/4)
        const int o0 = oq * OB;

        float acc[13];
#pragma unroll
        for (int i = 0; i < 13; i++) acc[i] = 0.0f;

        for (int k0 = 0; k0 < R_DIM; k0 += KT) {
#pragma unroll
            for (int i = 0; i < 4; i++) {
                int idx = tid + NTHR * i;
                int rr = idx >> 4, c4 = idx & 15;
                float4 v = __ldcg((const float4*)(g_states + (size_t)(t0 + rr) * R_DIM + k0) + c4);
                sm.gemm.s[rr][4 * c4 + 0] = v.x;
                sm.gemm.s[rr][4 * c4 + 1] = v.y;
                sm.gemm.s[rr][4 * c4 + 2] = v.z;
                sm.gemm.s[rr][4 * c4 + 3] = v.w;
            }
            for (int idx = tid; idx < O_DIM * (KT / 4); idx += NTHR) {
                int rr = idx >> 4, c4 = idx & 15;
                float4 v = __ldcg((const float4*)(g_Wc + (size_t)rr * R_DIM + k0) + c4);
                ((float4*)&sm.gemm.wc[rr][0])[c4] = v;
            }
            __syncthreads();
#pragma unroll 4
            for (int kk = 0; kk < KT; kk++) {
                float sv = sm.gemm.s[r][kk];
#pragma unroll
                for (int i = 0; i < 13; i++) {
                    int o = o0 + i;
                    if (o < O_DIM) acc[i] += sv * sm.gemm.wc[o][kk];
                }
            }
            __syncthreads();
        }
#pragma unroll
        for (int i = 0; i < 13; i++) {
            int o = o0 + i;
            if (o < O_DIM) out[(size_t)(t0 + r) * O_DIM + o] = acc[i] + __ldcg(&g_bc[o]);
        }
    }
#undef GBAR
}

// ---------------- launcher ----------------
extern "C" void kernel_launch(void* const* d_in, const int* in_sizes, int n_in,
                              void* d_out, int out_size) {
    (void)in_sizes; (void)n_in; (void)out_size;
    const float* x     = (const float*)d_in[0];
    const float* Win   = (const float*)d_in[1];
    const float* W     = (const float*)d_in[2];
    const float* fc1_w = (const float*)d_in[3];
    const float* fc1_b = (const float*)d_in[4];
    const float* fc2_w = (const float*)d_in[5];
    const float* fc2_b = (const float*)d_in[6];
    float* out = (float*)d_out;

    prep_kernel<<<1, 1>>>();
    fused_kernel<<<NBLK, NTHR>>>(x, Win, W, fc1_w, fc1_b, fc2_w, fc2_b, out);
}

// round 14
// speedup vs baseline: 1.7319x; 1.1739x over previous
#include <cuda_runtime.h>
#include <math.h>
#include <stdint.h>

#define S_LEN 16384
#define I_DIM 64
#define R_DIM 2048
#define H_DIM 128
#define O_DIM 50
#define NBLK  128
#define ROWS_PER_BLK 16   // 128*16 = 2048
#define NTHR  512
#define GT    128         // timesteps per block in output phase
#define KT    64

// ---------------- device scratch (static; no allocations) ----------------
__device__ float g_h[2][R_DIM];
__device__ float g_states[(size_t)S_LEN * R_DIM];   // 134 MB
__device__ float g_Wc[O_DIM * R_DIM];               // folded fc2@fc1
__device__ float g_bc[O_DIM];                       // folded bias
__device__ unsigned g_count = 0;                    // monotone across replays
__device__ unsigned g_base  = 0;                    // snapshot for this launch

// packed f32x2 FMA: d = a*b + d (sm_100+; only reachable via PTX)
__device__ __forceinline__ void ffma2(uint64_t& d, uint64_t a, uint64_t b) {
    asm("fma.rn.f32x2 %0, %1, %2, %0;" : "+l"(d) : "l"(a), "l"(b));
}
__device__ __forceinline__ unsigned ld_acquire_u32(const unsigned* p) {
    unsigned v;
    asm volatile("ld.acquire.gpu.global.u32 %0, [%1];" : "=r"(v) : "l"(p) : "memory");
    return v;
}
__device__ __forceinline__ void red_release_add(unsigned* p, unsigned v) {
    asm volatile("red.release.gpu.global.add.u32 [%0], %1;" :: "l"(p), "r"(v) : "memory");
}
// 16B L2 (cache-global) load as two packed u64
__device__ __forceinline__ void ldcg_v2u64(const void* p, uint64_t& a, uint64_t& b) {
    asm volatile("ld.global.cg.v2.u64 {%0,%1}, [%2];" : "=l"(a), "=l"(b) : "l"(p));
}
__device__ __forceinline__ float tanh_approx(float v) {
    float r;
    asm("tanh.approx.f32 %0, %1;" : "=f"(r) : "f"(v));
    return r;
}

// snapshot the barrier counter BEFORE the persistent kernel starts, so every
// block derives identical targets (kills the start-skew deadlock race).
__global__ void prep_kernel() { g_base = g_count; }

// ---------------- fused persistent kernel ----------------
union SmemU {
    float psum[ROWS_PER_BLK][4];                               // scan phase
    struct { float s[GT][KT + 1]; float wc[O_DIM][KT]; } gemm; // 46 KB
};

__global__ void __launch_bounds__(NTHR, 1) fused_kernel(
    const float* __restrict__ x,      // [S,64]
    const float* __restrict__ Win,    // [2048,64]
    const float* __restrict__ W,      // [2048,2048]
    const float* __restrict__ fc1_w,  // [128,2048]
    const float* __restrict__ fc1_b,  // [128]
    const float* __restrict__ fc2_w,  // [50,128]
    const float* __restrict__ fc2_b,  // [50]
    float* __restrict__ out)          // [S,50]
{
    __shared__ SmemU sm;

    const int tid  = threadIdx.x;
    const int lane = tid & 31;
    const int wrp  = tid >> 5;          // 0..15
    const int grp  = tid >> 7;          // 0..3
    const int tg   = tid & 127;         // 0..127
    const int wig  = wrp & 3;           // warp-in-group
    const int rbase = blockIdx.x * ROWS_PER_BLK;

    // identical for all blocks (set by prep_kernel); monotone + wrap-safe
    unsigned bar_tgt = g_base;

#define GBAR()                                                               \
    do {                                                                     \
        __syncthreads();                                                     \
        bar_tgt += NBLK;                                                     \
        if (wrp == 0) {                                                      \
            if (lane == 0) red_release_add(&g_count, 1u);                    \
            unsigned v;                                                      \
            do { v = ld_acquire_u32(&g_count); } while ((int)(v - bar_tgt) < 0); \
        }                                                                    \
        __syncthreads();                                                     \
    } while (0)

    // ---- Phase 0: W slice -> registers; Win fold weights; Wc/bc fold; h0 = 0
    uint64_t w2[4][8];
#pragma unroll
    for (int r = 0; r < 4; r++) {
        const ulonglong2* Wrow = (const ulonglong2*)(W + (size_t)(rbase + grp * 4 + r) * R_DIM);
#pragma unroll
        for (int j = 0; j < 4; j++) {
            ulonglong2 v = Wrow[tg + 128 * j];
            w2[r][2 * j]     = v.x;
            w2[r][2 * j + 1] = v.y;
        }
    }
    float wr[4] = {0.f, 0.f, 0.f, 0.f};
    if (tg < I_DIM) {
#pragma unroll
        for (int r = 0; r < 4; r++)
            wr[r] = __ldg(&Win[(size_t)(rbase + grp * 4 + r) * I_DIM + tg]);
    }
    // Wc fold: this block computes columns [rbase, rbase+16) for all 50 outputs
    for (int idx = tid; idx < O_DIM * ROWS_PER_BLK; idx += NTHR) {
        const int o  = idx >> 4;
        const int rr = idx & 15;
        float a = 0.f;
#pragma unroll 8
        for (int h = 0; h < H_DIM; h++)
            a += __ldg(&fc2_w[o * H_DIM + h]) * __ldg(&fc1_w[(size_t)h * R_DIM + rbase + rr]);
        g_Wc[o * R_DIM + rbase + rr] = a;
    }
    if (blockIdx.x == 0 && tid < O_DIM) {
        float b = __ldg(&fc2_b[tid]);
#pragma unroll 8
        for (int h = 0; h < H_DIM; h++) b += __ldg(&fc2_w[tid * H_DIM + h]) * __ldg(&fc1_b[h]);
        g_bc[tid] = b;
    }
    if (tid < ROWS_PER_BLK) g_h[0][rbase + tid] = 0.0f;

    GBAR();   // h0 + Wc published

    // ---- Phase 1: the scan
    float xv_next = (tg < I_DIM) ? __ldg(&x[tg]) : 0.f;   // x[0]
    float hold_reg = 0.0f;                                 // warp0 lanes<16

    for (int t = 0; t < S_LEN; t++) {
        const int p = t & 1;
        const float xv = xv_next;
        if (t + 1 < S_LEN && tg < I_DIM) xv_next = __ldg(&x[(size_t)(t + 1) * I_DIM + tg]);

        // h chunks straight from L2 (no SMEM staging)
        uint64_t h2[8];
        {
            const float4* hp = (const float4*)g_h[p];
#pragma unroll
            for (int j = 0; j < 4; j++)
                ldcg_v2u64(hp + tg + 128 * j, h2[2 * j], h2[2 * j + 1]);
        }

        float acc[4];
#pragma unroll
        for (int r = 0; r < 4; r++) {
            float2 seed = make_float2(wr[r] * xv, 0.f);   // xin folded in
            uint64_t a2 = *(uint64_t*)&seed;
#pragma unroll
            for (int j = 0; j < 8; j++) ffma2(a2, w2[r][j], h2[j]);
            float2 f = *(float2*)&a2;
            acc[r] = f.x + f.y;
        }
#pragma unroll
        for (int r = 0; r < 4; r++) {
            float a = acc[r];
#pragma unroll
            for (int s = 16; s > 0; s >>= 1) a += __shfl_xor_sync(0xffffffffu, a, s);
            if (lane == 0) sm.psum[grp * 4 + r][wig] = a;
        }
        __syncthreads();

        // finalize + barrier fused into warp 0 (others park at bar.sync)
        bar_tgt += NBLK;
        if (wrp == 0) {
            float hn = 0.f;
            if (lane < ROWS_PER_BLK) {
                const float4 ps = *(const float4*)sm.psum[lane];
                const float v  = (ps.x + ps.y) + (ps.z + ps.w);
                const float th = tanh_approx(v);             // MUFU.TANH
                hn = 0.5f * hold_reg + 0.5f * th;
                hold_reg = hn;
                g_h[p ^ 1][rbase + lane] = hn;         // only this 64B gates the release
            }
            __syncwarp(0xffffffffu);
            if (lane == 0) red_release_add(&g_count, 1u);
            if (lane < ROWS_PER_BLK)                    // ordered by NEXT release; fine
                g_states[(size_t)t * R_DIM + rbase + lane] = hn;
            unsigned v;
            do { v = ld_acquire_u32(&g_count); } while ((int)(v - bar_tgt) < 0);
        }
        __syncthreads();
    }

    GBAR();   // all states published

    // ---- Phase 2: out = states @ Wc^T + bc   (block handles GT timesteps)
    {
        const int t0 = blockIdx.x * GT;
        const int r  = tid & 127;            // row in tile
        const int oq = tid >> 7;             // 0..3
        const int OB = 13;                   // ceil(50/4)
        const int o0 = oq * OB;

        float acc[13];
#pragma unroll
        for (int i = 0; i < 13; i++) acc[i] = 0.0f;

        for (int k0 = 0; k0 < R_DIM; k0 += KT) {
#pragma unroll
            for (int i = 0; i < 4; i++) {
                int idx = tid + NTHR * i;
                int rr = idx >> 4, c4 = idx & 15;
                float4 v = __ldcg((const float4*)(g_states + (size_t)(t0 + rr) * R_DIM + k0) + c4);
                sm.gemm.s[rr][4 * c4 + 0] = v.x;
                sm.gemm.s[rr][4 * c4 + 1] = v.y;
                sm.gemm.s[rr][4 * c4 + 2] = v.z;
                sm.gemm.s[rr][4 * c4 + 3] = v.w;
            }
            for (int idx = tid; idx < O_DIM * (KT / 4); idx += NTHR) {
                int rr = idx >> 4, c4 = idx & 15;
                float4 v = __ldcg((const float4*)(g_Wc + (size_t)rr * R_DIM + k0) + c4);
                ((float4*)&sm.gemm.wc[rr][0])[c4] = v;
            }
            __syncthreads();
#pragma unroll 4
            for (int kk = 0; kk < KT; kk++) {
                float sv = sm.gemm.s[r][kk];
#pragma unroll
                for (int i = 0; i < 13; i++) {
                    int o = o0 + i;
                    if (o < O_DIM) acc[i] += sv * sm.gemm.wc[o][kk];
                }
            }
            __syncthreads();
        }
#pragma unroll
        for (int i = 0; i < 13; i++) {
            int o = o0 + i;
            if (o < O_DIM) out[(size_t)(t0 + r) * O_DIM + o] = acc[i] + __ldcg(&g_bc[o]);
        }
    }
#undef GBAR
}

// ---------------- launcher ----------------
extern "C" void kernel_launch(void* const* d_in, const int* in_sizes, int n_in,
                              void* d_out, int out_size) {
    (void)in_sizes; (void)n_in; (void)out_size;
    const float* x     = (const float*)d_in[0];
    const float* Win   = (const float*)d_in[1];
    const float* W     = (const float*)d_in[2];
    const float* fc1_w = (const float*)d_in[3];
    const float* fc1_b = (const float*)d_in[4];
    const float* fc2_w = (const float*)d_in[5];
    const float* fc2_b = (const float*)d_in[6];
    float* out = (float*)d_out;

    prep_kernel<<<1, 1>>>();
    fused_kernel<<<NBLK, NTHR>>>(x, Win, W, fc1_w, fc1_b, fc2_w, fc2_b, out);
}

// round 15
// speedup vs baseline: 1.9661x; 1.1352x over previous
#include <cuda_runtime.h>
#include <math.h>
#include <stdint.h>

#define S_LEN 16384
#define I_DIM 64
#define R_DIM 2048
#define H_DIM 128
#define O_DIM 50
#define NBLK  128
#define ROWS_PER_BLK 16   // 128*16 = 2048
#define NTHR  512
#define GT    128         // timesteps per block in output phase
#define KT    64
#define SENT  0x7FC0DEADu // NaN payload; |h|<1 so unreachable as a real h value

// ---------------- device scratch (static; no allocations) ----------------
__device__ float g_states[(size_t)S_LEN * R_DIM];   // 134 MB; also the h exchange
__device__ float g_Wc[O_DIM * R_DIM];               // folded fc2@fc1
__device__ float g_bc[O_DIM];                       // folded bias
__device__ unsigned g_count = 0;                    // monotone across replays
__device__ unsigned g_base  = 0;                    // snapshot for this launch

// packed f32x2 FMA: d = a*b + d (sm_100+; only reachable via PTX)
__device__ __forceinline__ void ffma2(uint64_t& d, uint64_t a, uint64_t b) {
    asm("fma.rn.f32x2 %0, %1, %2, %0;" : "+l"(d) : "l"(a), "l"(b));
}
__device__ __forceinline__ unsigned ld_acquire_u32(const unsigned* p) {
    unsigned v;
    asm volatile("ld.acquire.gpu.global.u32 %0, [%1];" : "=r"(v) : "l"(p) : "memory");
    return v;
}
__device__ __forceinline__ unsigned ld_relaxed_u32(const unsigned* p) {
    unsigned v;
    asm volatile("ld.relaxed.gpu.global.u32 %0, [%1];" : "=r"(v) : "l"(p) : "memory");
    return v;
}
__device__ __forceinline__ void red_release_add(unsigned* p, unsigned v) {
    asm volatile("red.release.gpu.global.add.u32 [%0], %1;" :: "l"(p), "r"(v) : "memory");
}
__device__ __forceinline__ void red_relaxed_add(unsigned* p, unsigned v) {
    asm volatile("red.relaxed.gpu.global.add.u32 [%0], %1;" :: "l"(p), "r"(v) : "memory");
}
__device__ __forceinline__ void ldcg_v4u32(const void* p, uint32_t& a, uint32_t& b,
                                           uint32_t& c, uint32_t& d) {
    asm volatile("ld.global.cg.v4.u32 {%0,%1,%2,%3}, [%4];"
                 : "=r"(a), "=r"(b), "=r"(c), "=r"(d) : "l"(p) : "memory");
}
__device__ __forceinline__ void stcg_f32(float* p, float v) {
    asm volatile("st.global.cg.f32 [%0], %1;" :: "l"(p), "f"(v) : "memory");
}
__device__ __forceinline__ float tanh_approx(float v) {
    float r;
    asm("tanh.approx.f32 %0, %1;" : "=f"(r) : "f"(v));
    return r;
}
__device__ __forceinline__ uint64_t pack64(uint32_t lo, uint32_t hi) {
    uint64_t r; asm("mov.b64 %0, {%1,%2};" : "=l"(r) : "r"(lo), "r"(hi)); return r;
}

// sentinel-fill g_states each launch; snapshot the barrier counter base
__global__ void fill_kernel() {
    if (blockIdx.x == 0 && threadIdx.x == 0) g_base = g_count;
    const size_t n4 = (size_t)S_LEN * R_DIM / 4;
    uint4* p = (uint4*)g_states;
    const uint4 s = make_uint4(SENT, SENT, SENT, SENT);
    const size_t stride = (size_t)gridDim.x * blockDim.x;
    for (size_t i = blockIdx.x * (size_t)blockDim.x + threadIdx.x; i < n4; i += stride)
        p[i] = s;
}

// ---------------- fused persistent kernel ----------------
union SmemU {
    float psum[ROWS_PER_BLK][4];                               // scan phase
    struct { float s[GT][KT + 1]; float wc[O_DIM][KT]; } gemm; // 46 KB
};

__global__ void __launch_bounds__(NTHR, 1) fused_kernel(
    const float* __restrict__ x,      // [S,64]
    const float* __restrict__ Win,    // [2048,64]
    const float* __restrict__ W,      // [2048,2048]
    const float* __restrict__ fc1_w,  // [128,2048]
    const float* __restrict__ fc1_b,  // [128]
    const float* __restrict__ fc2_w,  // [50,128]
    const float* __restrict__ fc2_b,  // [50]
    float* __restrict__ out)          // [S,50]
{
    __shared__ SmemU sm;

    const int tid  = threadIdx.x;
    const int lane = tid & 31;
    const int wrp  = tid >> 5;          // 0..15
    const int grp  = tid >> 7;          // 0..3
    const int tg   = tid & 127;         // 0..127
    const int wig  = wrp & 3;           // warp-in-group
    const int rbase = blockIdx.x * ROWS_PER_BLK;

    unsigned bar_tgt = g_base;   // identical for all blocks; monotone + wrap-safe

    // full-ordering barrier for phase transitions (release arrivals, acquire poll)
#define GBAR()                                                               \
    do {                                                                     \
        __syncthreads();                                                     \
        bar_tgt += NBLK;                                                     \
        if (wrp == 0) {                                                      \
            if (lane == 0) red_release_add(&g_count, 1u);                    \
            unsigned v;                                                      \
            do { v = ld_acquire_u32(&g_count); } while ((int)(v - bar_tgt) < 0); \
        }                                                                    \
        __syncthreads();                                                     \
    } while (0)

    // ---- Phase 0: W slice -> registers; Win fold weights; Wc/bc fold
    uint64_t w2[4][8];
#pragma unroll
    for (int r = 0; r < 4; r++) {
        const ulonglong2* Wrow = (const ulonglong2*)(W + (size_t)(rbase + grp * 4 + r) * R_DIM);
#pragma unroll
        for (int j = 0; j < 4; j++) {
            ulonglong2 v = Wrow[tg + 128 * j];
            w2[r][2 * j]     = v.x;
            w2[r][2 * j + 1] = v.y;
        }
    }
    float wr[4] = {0.f, 0.f, 0.f, 0.f};
    if (tg < I_DIM) {
#pragma unroll
        for (int r = 0; r < 4; r++)
            wr[r] = __ldg(&Win[(size_t)(rbase + grp * 4 + r) * I_DIM + tg]);
    }
    // Wc fold: this block computes columns [rbase, rbase+16) for all 50 outputs
    for (int idx = tid; idx < O_DIM * ROWS_PER_BLK; idx += NTHR) {
        const int o  = idx >> 4;
        const int rr = idx & 15;
        float a = 0.f;
#pragma unroll 8
        for (int h = 0; h < H_DIM; h++)
            a += __ldg(&fc2_w[o * H_DIM + h]) * __ldg(&fc1_w[(size_t)h * R_DIM + rbase + rr]);
        g_Wc[o * R_DIM + rbase + rr] = a;
    }
    if (blockIdx.x == 0 && tid < O_DIM) {
        float b = __ldg(&fc2_b[tid]);
#pragma unroll 8
        for (int h = 0; h < H_DIM; h++) b += __ldg(&fc2_w[tid * H_DIM + h]) * __ldg(&fc1_b[h]);
        g_bc[tid] = b;
    }

    GBAR();   // Wc/bc ready; also guarantees fill_kernel's sentinels are visible

    // ---- Phase 1: scan. Pacing barrier (early-arrive, relaxed) + value-
    //      validated h exchange through g_states (sentinel spin, short window).
    float xv_next = (tg < I_DIM) ? __ldg(&x[tg]) : 0.f;   // x[0]
    float hold_reg = 0.0f;                                 // warp0 lanes<16

    for (int t = 0; t < S_LEN; t++) {
        const float xv = xv_next;
        if (t + 1 < S_LEN && tg < I_DIM) xv_next = __ldg(&x[(size_t)(t + 1) * I_DIM + tg]);

        uint64_t h2[8];
        if (t > 0) {
            const uint4* hrow = (const uint4*)(g_states + (size_t)(t - 1) * R_DIM);
            uint32_t vx[4], vy[4], vz[4], vw[4];
#pragma unroll
            for (int j = 0; j < 4; j++)
                ldcg_v4u32(hrow + tg + 128 * j, vx[j], vy[j], vz[j], vw[j]);
            unsigned pend = 0xFu;
            while (pend) {
#pragma unroll
                for (int j = 0; j < 4; j++) {
                    if (pend & (1u << j)) {
                        if ((vx[j] != SENT) & (vy[j] != SENT) & (vz[j] != SENT) & (vw[j] != SENT))
                            pend &= ~(1u << j);
                        else
                            ldcg_v4u32(hrow + tg + 128 * j, vx[j], vy[j], vz[j], vw[j]);
                    }
                }
            }
#pragma unroll
            for (int j = 0; j < 4; j++) {
                h2[2 * j]     = pack64(vx[j], vy[j]);
                h2[2 * j + 1] = pack64(vz[j], vw[j]);
            }
        } else {
#pragma unroll
            for (int j = 0; j < 8; j++) h2[j] = 0ull;
        }

        float acc[4];
#pragma unroll
        for (int r = 0; r < 4; r++) {
            float2 seed = make_float2(wr[r] * xv, 0.f);   // xin folded in
            uint64_t a2 = *(uint64_t*)&seed;
#pragma unroll
            for (int j = 0; j < 8; j++) ffma2(a2, w2[r][j], h2[j]);
            float2 f = *(float2*)&a2;
            acc[r] = f.x + f.y;
        }
#pragma unroll
        for (int r = 0; r < 4; r++) {
            float a = acc[r];
#pragma unroll
            for (int s = 16; s > 0; s >>= 1) a += __shfl_xor_sync(0xffffffffu, a, s);
            if (lane == 0) sm.psum[grp * 4 + r][wig] = a;
        }
        __syncthreads();

        // pacing barrier: ARRIVE FIRST (relaxed), then finalize+publish, then poll.
        // Count propagation overlaps finalize/store; data validity = sentinel check.
        bar_tgt += NBLK;
        if (wrp == 0) {
            if (lane == 0) red_relaxed_add(&g_count, 1u);   // early arrival
            if (lane < ROWS_PER_BLK) {
                const float4 ps = *(const float4*)sm.psum[lane];
                const float v  = (ps.x + ps.y) + (ps.z + ps.w);
                const float th = tanh_approx(v);             // MUFU.TANH
                const float hn = 0.5f * hold_reg + 0.5f * th;
                hold_reg = hn;
                stcg_f32(&g_states[(size_t)t * R_DIM + rbase + lane], hn);  // publish
            }
            unsigned v;
            do { v = ld_relaxed_u32(&g_count); } while ((int)(v - bar_tgt) < 0);
        }
        __syncthreads();
    }

    GBAR();   // release/acquire: all h stores globally visible for phase 2

    // ---- Phase 2: out = states @ Wc^T + bc   (block handles GT timesteps)
    {
        const int t0 = blockIdx.x * GT;
        const int r  = tid & 127;            // row in tile
        const int oq = tid >> 7;             // 0..3
        const int OB = 13;                   // ceil(50/4)
        const int o0 = oq * OB;

        float acc[13];
#pragma unroll
        for (int i = 0; i < 13; i++) acc[i] = 0.0f;

        for (int k0 = 0; k0 < R_DIM; k0 += KT) {
#pragma unroll
            for (int i = 0; i < 4; i++) {
                int idx = tid + NTHR * i;
                int rr = idx >> 4, c4 = idx & 15;
                float4 v = __ldcg((const float4*)(g_states + (size_t)(t0 + rr) * R_DIM + k0) + c4);
                sm.gemm.s[rr][4 * c4 + 0] = v.x;
                sm.gemm.s[rr][4 * c4 + 1] = v.y;
                sm.gemm.s[rr][4 * c4 + 2] = v.z;
                sm.gemm.s[rr][4 * c4 + 3] = v.w;
            }
            for (int idx = tid; idx < O_DIM * (KT / 4); idx += NTHR) {
                int rr = idx >> 4, c4 = idx & 15;
                float4 v = __ldcg((const float4*)(g_Wc + (size_t)rr * R_DIM + k0) + c4);
                ((float4*)&sm.gemm.wc[rr][0])[c4] = v;
            }
            __syncthreads();
#pragma unroll 4
            for (int kk = 0; kk < KT; kk++) {
                float sv = sm.gemm.s[r][kk];
#pragma unroll
                for (int i = 0; i < 13; i++) {
                    int o = o0 + i;
                    if (o < O_DIM) acc[i] += sv * sm.gemm.wc[o][kk];
                }
            }
            __syncthreads();
        }
#pragma unroll
        for (int i = 0; i < 13; i++) {
            int o = o0 + i;
            if (o < O_DIM) out[(size_t)(t0 + r) * O_DIM + o] = acc[i] + __ldcg(&g_bc[o]);
        }
    }
#undef GBAR
}

// ---------------- launcher ----------------
extern "C" void kernel_launch(void* const* d_in, const int* in_sizes, int n_in,
                              void* d_out, int out_size) {
    (void)in_sizes; (void)n_in; (void)out_size;
    const float* x     = (const float*)d_in[0];
    const float* Win   = (const float*)d_in[1];
    const float* W     = (const float*)d_in[2];
    const float* fc1_w = (const float*)d_in[3];
    const float* fc1_b = (const float*)d_in[4];
    const float* fc2_w = (const float*)d_in[5];
    const float* fc2_b = (const float*)d_in[6];
    float* out = (float*)d_out;

    fill_kernel<<<1024, 512>>>();          // sentinel-fill + base snapshot (per replay)
    fused_kernel<<<NBLK, NTHR>>>(x, Win, W, fc1_w, fc1_b, fc2_w, fc2_b, out);
}